// round 2
// baseline (speedup 1.0000x reference)
#include <cuda_runtime.h>
#include <math.h>

#define B_  16384
#define I_  1280
#define H_  320
#define D_  4
#define U1_ 512
#define U2_ 256
#define U3_ 128

// ---------------- scratch (device globals; no allocation allowed) ----------
__device__ int   g_perm[B_];
__device__ int   g_count[D_];
__device__ int   g_base[D_];
__device__ int   g_cursor[D_];
__device__ float g_h [B_ * H_];      // 21 MB
__device__ float g_s [B_ * I_];      // 84 MB (pruned embedding, permuted order)
__device__ float g_x1[B_ * U1_];     // 33.5 MB
__device__ float g_x2[B_ * U2_];     // 16.8 MB
__device__ float g_x3[B_ * U3_];     //  8.4 MB

__device__ __forceinline__ float* buf_ptr(int id) {
    switch (id) {
        case 0: return g_h;
        case 1: return g_s;
        case 2: return g_x1;
        case 3: return g_x2;
        case 4: return g_x3;
    }
    return nullptr;
}

// ---------------- domain binning (counting sort, order-independent) --------
__global__ void k_init() {
    if (threadIdx.x < D_) { g_count[threadIdx.x] = 0; g_cursor[threadIdx.x] = 0; }
}
__global__ void k_count(const int* __restrict__ dom) {
    int i = blockIdx.x * 256 + threadIdx.x;
    if (i < B_) {
        int d = dom[i]; d = d < 0 ? 0 : (d > D_ - 1 ? D_ - 1 : d);
        atomicAdd(&g_count[d], 1);
    }
}
__global__ void k_scan() {
    if (threadIdx.x == 0) {
        int s = 0;
        for (int d = 0; d < D_; d++) { g_base[d] = s; s += g_count[d]; }
    }
}
__global__ void k_scatter(const int* __restrict__ dom) {
    int i = blockIdx.x * 256 + threadIdx.x;
    if (i < B_) {
        int d = dom[i]; d = d < 0 ? 0 : (d > D_ - 1 ? D_ - 1 : d);
        int p = g_base[d] + atomicAdd(&g_cursor[d], 1);
        g_perm[p] = i;
    }
}

// ---------------- fused tiled GEMM (double-buffered) ----------------------
// C[M,N] = epilogue(A[M,K] @ W[K,N] + bias)
// Tile 128x64x16, 256 threads, 8x4 per-thread micro-tile, 2-stage smem
// pipeline (one __syncthreads per k-iteration; gmem prefetch overlaps FMA).
// SEG:    rows come from per-domain segment bz (g_base/g_count); W/bias get
//         a per-domain stride. Grid covers worst case; empty tiles exit.
// GATHER: A rows are indirected through g_perm (used when A = original emb).
// EPI_RELU:  C = max(acc + b, 0)
// EPI_PRUNE: z = acc + b;  C = (z > 0) ? emb[perm[row]] * sigmoid(z) : 0
#define EPI_RELU  0
#define EPI_PRUNE 1

template<bool SEG, bool GATHER, int EPI>
__global__ __launch_bounds__(256)
void gemm_kernel(const float* __restrict__ Aext, int aid, int lda,
                 const float* __restrict__ W, long wstride,
                 const float* __restrict__ bias, int bstride,
                 int cid, int ldc,
                 const float* __restrict__ emb,
                 int N, int K)
{
    __shared__ float As[2][16][128];   // transposed: As[s][k][m]
    __shared__ float Bs[2][16][64];

    const int t = threadIdx.x;
    int bz = SEG ? blockIdx.z : 0;
    int segBase = 0, segCnt = B_;
    if (SEG) { segCnt = g_count[bz]; segBase = g_base[bz]; }

    const int m0 = blockIdx.y * 128;
    if (m0 >= segCnt) return;                 // uniform per block
    const int n0 = blockIdx.x * 64;

    const float* A  = (aid >= 0) ? buf_ptr(aid) : Aext;
    const float* Wp = W + (long)bz * wstride;
    const float* bp = bias + bz * bstride;

    // A-load role: thread t loads 8 consecutive floats of row (t>>1),
    // halves selected by (t&1).
    const int  arow   = t >> 1;
    const int  ac     = (t & 1) * 8;
    const bool rvalid = (m0 + arow) < segCnt;
    const float* Arow = A;
    if (rvalid) {
        int pos  = segBase + m0 + arow;
        int grow = GATHER ? g_perm[pos] : pos;
        Arow = A + (size_t)grow * lda;
    }
    // B-load role: thread t loads float4 at Bs[t>>4][(t&15)*4].
    const int br = t >> 4;
    const int bc = (t & 15) * 4;
    // compute role
    const int tx = t & 15;   // 16 * 4 = 64 cols
    const int ty = t >> 4;   // 16 * 8 = 128 rows

    float acc[8][4];
#pragma unroll
    for (int i = 0; i < 8; i++)
#pragma unroll
        for (int j = 0; j < 4; j++) acc[i][j] = 0.f;

    // ---- prologue: stage k-tile 0 into buffer 0 ----
    float4 av0 = make_float4(0.f, 0.f, 0.f, 0.f), av1 = av0;
    if (rvalid) {
        av0 = *reinterpret_cast<const float4*>(Arow + ac);
        av1 = *reinterpret_cast<const float4*>(Arow + ac + 4);
    }
    float4 bv = *reinterpret_cast<const float4*>(Wp + (size_t)br * N + n0 + bc);
    As[0][ac + 0][arow] = av0.x; As[0][ac + 1][arow] = av0.y;
    As[0][ac + 2][arow] = av0.z; As[0][ac + 3][arow] = av0.w;
    As[0][ac + 4][arow] = av1.x; As[0][ac + 5][arow] = av1.y;
    As[0][ac + 6][arow] = av1.z; As[0][ac + 7][arow] = av1.w;
    *reinterpret_cast<float4*>(&Bs[0][br][bc]) = bv;
    __syncthreads();

    int cur = 0;
    for (int k0 = 0; k0 < K; k0 += 16) {
        // prefetch next k-tile into registers (overlaps with FMA below)
        const bool more = (k0 + 16) < K;
        if (more) {
            if (rvalid) {
                av0 = *reinterpret_cast<const float4*>(Arow + k0 + 16 + ac);
                av1 = *reinterpret_cast<const float4*>(Arow + k0 + 16 + ac + 4);
            }
            bv = *reinterpret_cast<const float4*>(
                     Wp + (size_t)(k0 + 16 + br) * N + n0 + bc);
        }

#pragma unroll
        for (int k = 0; k < 16; k++) {
            float4 a0 = *reinterpret_cast<const float4*>(&As[cur][k][ty * 8]);
            float4 a1 = *reinterpret_cast<const float4*>(&As[cur][k][ty * 8 + 4]);
            float4 b  = *reinterpret_cast<const float4*>(&Bs[cur][k][tx * 4]);
            float am[8] = {a0.x, a0.y, a0.z, a0.w, a1.x, a1.y, a1.z, a1.w};
            float bm[4] = {b.x, b.y, b.z, b.w};
#pragma unroll
            for (int i = 0; i < 8; i++)
#pragma unroll
                for (int j = 0; j < 4; j++)
                    acc[i][j] = fmaf(am[i], bm[j], acc[i][j]);
        }

        if (more) {
            int nxt = cur ^ 1;
            // safe without a pre-sync: everyone finished READING buffer `nxt`
            // before the __syncthreads at the end of the previous iteration.
            As[nxt][ac + 0][arow] = av0.x; As[nxt][ac + 1][arow] = av0.y;
            As[nxt][ac + 2][arow] = av0.z; As[nxt][ac + 3][arow] = av0.w;
            As[nxt][ac + 4][arow] = av1.x; As[nxt][ac + 5][arow] = av1.y;
            As[nxt][ac + 6][arow] = av1.z; As[nxt][ac + 7][arow] = av1.w;
            *reinterpret_cast<float4*>(&Bs[nxt][br][bc]) = bv;
            __syncthreads();
            cur = nxt;
        }
    }

    float* C = buf_ptr(cid);
    float4 b4 = *reinterpret_cast<const float4*>(bp + n0 + tx * 4);
    float bb[4] = {b4.x, b4.y, b4.z, b4.w};

#pragma unroll
    for (int i = 0; i < 8; i++) {
        int mloc = ty * 8 + i;
        if (m0 + mloc >= segCnt) continue;
        int pos = segBase + m0 + mloc;
        float4 st;
        float* stp = &st.x;
        if (EPI == EPI_RELU) {
#pragma unroll
            for (int j = 0; j < 4; j++)
                stp[j] = fmaxf(acc[i][j] + bb[j], 0.f);
        } else {
            int grow = g_perm[pos];
            float4 e = *reinterpret_cast<const float4*>(
                emb + (size_t)grow * I_ + n0 + tx * 4);
            const float* ep = &e.x;
#pragma unroll
            for (int j = 0; j < 4; j++) {
                float z = acc[i][j] + bb[j];
                float w = 1.f / (1.f + expf(-z));   // sigmoid(z) > 0.5 <=> z > 0
                stp[j] = (z > 0.f) ? ep[j] * w : 0.f;
            }
        }
        *reinterpret_cast<float4*>(C + (size_t)pos * ldc + n0 + tx * 4) = st;
    }
}

// ---------------- final 128-dot + sigmoid + scatter -----------------------
__global__ void final_kernel(const float* __restrict__ w4,
                             const float* __restrict__ b4,
                             float* __restrict__ out)
{
    int warp = blockIdx.x * 8 + (threadIdx.x >> 5);
    int lane = threadIdx.x & 31;
    float4 x = *reinterpret_cast<const float4*>(g_x3 + (size_t)warp * U3_ + lane * 4);
    float4 w = *reinterpret_cast<const float4*>(w4 + lane * 4);
    float s = x.x * w.x + x.y * w.y + x.z * w.z + x.w * w.w;
#pragma unroll
    for (int o = 16; o; o >>= 1) s += __shfl_xor_sync(0xffffffffu, s, o);
    if (lane == 0)
        out[g_perm[warp]] = 1.f / (1.f + expf(-(s + b4[0])));
}

// ---------------- launch ---------------------------------------------------
extern "C" void kernel_launch(void* const* d_in, const int* in_sizes, int n_in,
                              void* d_out, int out_size)
{
    const float* emb  = (const float*)d_in[0];
    const int*   dom  = (const int*)  d_in[1];
    const float* p_w1 = (const float*)d_in[2];
    const float* p_b1 = (const float*)d_in[3];
    const float* p_w2 = (const float*)d_in[4];
    const float* p_b2 = (const float*)d_in[5];
    const float* d_w1 = (const float*)d_in[6];
    const float* d_b1 = (const float*)d_in[7];
    const float* d_w2 = (const float*)d_in[8];
    const float* d_b2 = (const float*)d_in[9];
    const float* d_w3 = (const float*)d_in[10];
    const float* d_b3 = (const float*)d_in[11];
    const float* d_w4 = (const float*)d_in[12];
    const float* d_b4 = (const float*)d_in[13];
    float* out = (float*)d_out;

    // 1) bin rows by domain
    k_init   <<<1, 32>>>();
    k_count  <<<(B_ + 255) / 256, 256>>>(dom);
    k_scan   <<<1, 32>>>();
    k_scatter<<<(B_ + 255) / 256, 256>>>(dom);

    // 2) pruner layer 1: h = relu(emb[perm] @ p_w1[d] + p_b1[d])   [B,320]
    gemm_kernel<true, true, EPI_RELU>
        <<<dim3(H_ / 64, B_ / 128, D_), 256>>>(
            emb, -1, I_, p_w1, (long)I_ * H_, p_b1, H_,
            /*cid=*/0, H_, nullptr, H_, I_);

    // 3) pruner layer 2 + prune: s = emb * sigmoid(z) * (z>0)       [B,1280]
    gemm_kernel<true, false, EPI_PRUNE>
        <<<dim3(I_ / 64, B_ / 128, D_), 256>>>(
            nullptr, 0, H_, p_w2, (long)H_ * I_, p_b2, I_,
            /*cid=*/1, I_, emb, I_, H_);

    // 4) shared MLP
    gemm_kernel<false, false, EPI_RELU>
        <<<dim3(U1_ / 64, B_ / 128, 1), 256>>>(
            nullptr, 1, I_, d_w1, 0, d_b1, 0, /*cid=*/2, U1_, nullptr, U1_, I_);
    gemm_kernel<false, false, EPI_RELU>
        <<<dim3(U2_ / 64, B_ / 128, 1), 256>>>(
            nullptr, 2, U1_, d_w2, 0, d_b2, 0, /*cid=*/3, U2_, nullptr, U2_, U1_);
    gemm_kernel<false, false, EPI_RELU>
        <<<dim3(U3_ / 64, B_ / 128, 1), 256>>>(
            nullptr, 3, U2_, d_w3, 0, d_b3, 0, /*cid=*/4, U3_, nullptr, U3_, U2_);

    // 5) logits + sigmoid + scatter to original rows
    final_kernel<<<B_ / 8, 256>>>(d_w4, d_b4, out);
}

// round 4
// speedup vs baseline: 3.5967x; 3.5967x over previous
#include <cuda_runtime.h>
#include <cuda_bf16.h>
#include <cstdint>
#include <math.h>

#define B_  16384
#define I_  1280
#define H_  320
#define D_  4
#define U1_ 512
#define U2_ 256
#define U3_ 128

// ---------------- scratch (device globals; no allocation allowed) ----------
__device__ int g_perm[B_];
__device__ int g_count[D_], g_base[D_], g_cursor[D_];

__device__ __nv_bfloat16 g_h  [B_ * H_];
__device__ __nv_bfloat16 g_s  [B_ * I_];
__device__ __nv_bfloat16 g_x1 [B_ * U1_];
__device__ __nv_bfloat16 g_x2 [B_ * U2_];
__device__ __nv_bfloat16 g_x3 [B_ * U3_];
__device__ __nv_bfloat16 g_ebf[B_ * I_];
__device__ __nv_bfloat16 g_pw1[D_ * I_ * H_];
__device__ __nv_bfloat16 g_pw2[D_ * H_ * I_];
__device__ __nv_bfloat16 g_dw1[I_ * U1_];
__device__ __nv_bfloat16 g_dw2[U1_ * U2_];
__device__ __nv_bfloat16 g_dw3[U2_ * U3_];

__device__ __forceinline__ __nv_bfloat16* bfbuf(int id) {
    switch (id) {
        case 0: return g_h;   case 1: return g_s;   case 2: return g_x1;
        case 3: return g_x2;  case 4: return g_x3;  case 5: return g_ebf;
        case 6: return g_pw1; case 7: return g_pw2; case 8: return g_dw1;
        case 9: return g_dw2; case 10: return g_dw3;
    }
    return nullptr;
}

// ---------------- fp32 -> bf16 conversion ----------------------------------
__global__ void f2bf(const float* __restrict__ src, int dstid, int n) {
    int i = (blockIdx.x * 256 + threadIdx.x) * 4;
    if (i >= n) return;
    float4 v = *reinterpret_cast<const float4*>(src + i);
    __nv_bfloat16* d = bfbuf(dstid) + i;
    *reinterpret_cast<__nv_bfloat162*>(d)     = __floats2bfloat162_rn(v.x, v.y);
    *reinterpret_cast<__nv_bfloat162*>(d + 2) = __floats2bfloat162_rn(v.z, v.w);
}

// ---------------- domain binning (counting sort, order-independent) --------
__global__ void k_init() {
    if (threadIdx.x < D_) { g_count[threadIdx.x] = 0; g_cursor[threadIdx.x] = 0; }
}
__global__ void k_count(const int* __restrict__ dom) {
    int i = blockIdx.x * 256 + threadIdx.x;
    if (i < B_) {
        int d = dom[i]; d = d < 0 ? 0 : (d > D_ - 1 ? D_ - 1 : d);
        atomicAdd(&g_count[d], 1);
    }
}
__global__ void k_scan() {
    if (threadIdx.x == 0) {
        int s = 0;
        for (int d = 0; d < D_; d++) { g_base[d] = s; s += g_count[d]; }
    }
}
__global__ void k_scatter(const int* __restrict__ dom) {
    int i = blockIdx.x * 256 + threadIdx.x;
    if (i < B_) {
        int d = dom[i]; d = d < 0 ? 0 : (d > D_ - 1 ? D_ - 1 : d);
        int p = g_base[d] + atomicAdd(&g_cursor[d], 1);
        g_perm[p] = i;
    }
}

// ---------------- tensor-core primitives -----------------------------------
__device__ __forceinline__ void ldsm4(uint32_t& r0, uint32_t& r1,
                                      uint32_t& r2, uint32_t& r3, uint32_t a) {
    asm volatile("ldmatrix.sync.aligned.m8n8.x4.shared.b16 {%0,%1,%2,%3}, [%4];"
                 : "=r"(r0), "=r"(r1), "=r"(r2), "=r"(r3) : "r"(a));
}
__device__ __forceinline__ void ldsm4t(uint32_t& r0, uint32_t& r1,
                                       uint32_t& r2, uint32_t& r3, uint32_t a) {
    asm volatile("ldmatrix.sync.aligned.m8n8.x4.trans.shared.b16 {%0,%1,%2,%3}, [%4];"
                 : "=r"(r0), "=r"(r1), "=r"(r2), "=r"(r3) : "r"(a));
}
__device__ __forceinline__ void mma_bf16(float* c,
                                         uint32_t a0, uint32_t a1, uint32_t a2, uint32_t a3,
                                         uint32_t b0, uint32_t b1) {
    asm volatile("mma.sync.aligned.m16n8k16.row.col.f32.bf16.bf16.f32 "
                 "{%0,%1,%2,%3}, {%4,%5,%6,%7}, {%8,%9}, {%0,%1,%2,%3};"
                 : "+f"(c[0]), "+f"(c[1]), "+f"(c[2]), "+f"(c[3])
                 : "r"(a0), "r"(a1), "r"(a2), "r"(a3), "r"(b0), "r"(b1));
}

// ---------------- bf16 tensor-core GEMM ------------------------------------
// C[M,N](bf16) = epilogue(A[M,K](bf16) @ W[K,N](bf16) + bias(fp32))
// Block tile 128x64x32, 256 threads = 8 warps (4x2), warp tile 32x32,
// mma m16n8k16, fp32 accum. Double-buffered smem w/ register prefetch.
// A smem rows padded to 40 elems (80B), B rows to 72 elems (144B):
// conflict-free ldmatrix.
#define EPI_RELU  0
#define EPI_PRUNE 1
#define LDA_PAD 40
#define LDB_PAD 72

template<bool SEG, bool GATHER, int EPI>
__global__ __launch_bounds__(256)
void gemm_bf16(int aid, int lda, int wid, long wstride,
               const float* __restrict__ bias, int bstride,
               int cid, int ldc, int N, int K)
{
    __shared__ __nv_bfloat16 As[2][128 * LDA_PAD];
    __shared__ __nv_bfloat16 Bs[2][32 * LDB_PAD];

    const int t = threadIdx.x;
    int bz = SEG ? blockIdx.z : 0;
    int segBase = 0, segCnt = B_;
    if (SEG) { segCnt = g_count[bz]; segBase = g_base[bz]; }

    const int m0 = blockIdx.y * 128;
    if (m0 >= segCnt) return;                 // uniform per block
    const int n0 = blockIdx.x * 64;

    const __nv_bfloat16* A  = bfbuf(aid);
    const __nv_bfloat16* Wp = bfbuf(wid) + (long)bz * wstride;
    const float*         bp = bias + bz * bstride;

    // ---- staging roles ----
    // A: 512 16B-chunks (128 rows x 4); thread t handles chunks t and t+256.
    const int  ar0 = t >> 2, ar1 = 64 + (t >> 2);
    const int  ac8 = (t & 3) * 8;
    const bool v0 = (m0 + ar0) < segCnt, v1 = (m0 + ar1) < segCnt;
    const __nv_bfloat16 *Ap0 = A, *Ap1 = A;
    if (v0) {
        int p = segBase + m0 + ar0;
        int gr = GATHER ? g_perm[p] : p;
        Ap0 = A + (size_t)gr * lda;
    }
    if (v1) {
        int p = segBase + m0 + ar1;
        int gr = GATHER ? g_perm[p] : p;
        Ap1 = A + (size_t)gr * lda;
    }
    // B: 256 16B-chunks (32 rows x 8); thread t handles chunk t.
    const int br = t >> 3, bc8 = (t & 7) * 8;
    const __nv_bfloat16* Bg = Wp + (size_t)br * N + n0 + bc8;

    // ---- prologue: k-tile 0 into buffer 0 ----
    uint4 pa0 = make_uint4(0, 0, 0, 0), pa1 = pa0, pb;
    if (v0) pa0 = *reinterpret_cast<const uint4*>(Ap0 + ac8);
    if (v1) pa1 = *reinterpret_cast<const uint4*>(Ap1 + ac8);
    pb = *reinterpret_cast<const uint4*>(Bg);

    *reinterpret_cast<uint4*>(&As[0][ar0 * LDA_PAD + ac8]) = pa0;
    *reinterpret_cast<uint4*>(&As[0][ar1 * LDA_PAD + ac8]) = pa1;
    *reinterpret_cast<uint4*>(&Bs[0][br * LDB_PAD + bc8])  = pb;
    __syncthreads();

    const uint32_t sA = (uint32_t)__cvta_generic_to_shared(&As[0][0]);
    const uint32_t sB = (uint32_t)__cvta_generic_to_shared(&Bs[0][0]);

    const int lane = t & 31, warp = t >> 5;
    const int wm = warp >> 1, wn = warp & 1;        // 4x2 warp grid
    const int aRowOff = lane & 15;                  // + wm*32 + mt*16
    const int aColOff = (lane >> 4) * 8;            // + ks*16
    const int bRowOff = (lane & 7) + ((lane >> 3) & 1) * 8;  // + ks*16
    const int bColOff = wn * 32 + (lane >> 4) * 8;  // + np*16

    float acc[2][4][4];
#pragma unroll
    for (int i = 0; i < 2; i++)
#pragma unroll
        for (int j = 0; j < 4; j++)
#pragma unroll
            for (int k = 0; k < 4; k++) acc[i][j][k] = 0.f;

    int cur = 0;
    for (int k0 = 0; k0 < K; k0 += 32) {
        const bool more = (k0 + 32) < K;
        if (more) {   // register prefetch of next k-tile (overlaps mma)
            if (v0) pa0 = *reinterpret_cast<const uint4*>(Ap0 + k0 + 32 + ac8);
            if (v1) pa1 = *reinterpret_cast<const uint4*>(Ap1 + k0 + 32 + ac8);
            pb = *reinterpret_cast<const uint4*>(Bg + (size_t)(k0 + 32) * N);
        }

        const uint32_t baseA = sA + cur * (128 * LDA_PAD * 2);
        const uint32_t baseB = sB + cur * (32 * LDB_PAD * 2);
#pragma unroll
        for (int ks = 0; ks < 2; ks++) {
            uint32_t a[2][4], b[2][4];
#pragma unroll
            for (int mt = 0; mt < 2; mt++) {
                uint32_t addr = baseA +
                    (((wm * 32 + mt * 16 + aRowOff) * LDA_PAD + ks * 16 + aColOff) << 1);
                ldsm4(a[mt][0], a[mt][1], a[mt][2], a[mt][3], addr);
            }
#pragma unroll
            for (int np = 0; np < 2; np++) {
                uint32_t addr = baseB +
                    (((ks * 16 + bRowOff) * LDB_PAD + bColOff + np * 16) << 1);
                ldsm4t(b[np][0], b[np][1], b[np][2], b[np][3], addr);
            }
#pragma unroll
            for (int mt = 0; mt < 2; mt++)
#pragma unroll
                for (int np = 0; np < 2; np++) {
                    mma_bf16(acc[mt][np * 2],
                             a[mt][0], a[mt][1], a[mt][2], a[mt][3],
                             b[np][0], b[np][1]);
                    mma_bf16(acc[mt][np * 2 + 1],
                             a[mt][0], a[mt][1], a[mt][2], a[mt][3],
                             b[np][2], b[np][3]);
                }
        }

        if (more) {
            int nxt = cur ^ 1;
            *reinterpret_cast<uint4*>(&As[nxt][ar0 * LDA_PAD + ac8]) = pa0;
            *reinterpret_cast<uint4*>(&As[nxt][ar1 * LDA_PAD + ac8]) = pa1;
            *reinterpret_cast<uint4*>(&Bs[nxt][br * LDB_PAD + bc8])  = pb;
            __syncthreads();
            cur = nxt;
        }
    }

    // ---- epilogue ----
    __nv_bfloat16* C = bfbuf(cid);
    const int g = lane >> 2, tig = lane & 3;
#pragma unroll
    for (int mt = 0; mt < 2; mt++) {
#pragma unroll
        for (int nt = 0; nt < 4; nt++) {
            const int col = n0 + wn * 32 + nt * 8 + tig * 2;
            const float bb0 = bp[col], bb1 = bp[col + 1];
#pragma unroll
            for (int hf = 0; hf < 2; hf++) {
                const int rl = wm * 32 + mt * 16 + g + hf * 8;
                if (m0 + rl >= segCnt) continue;
                const int pos = segBase + m0 + rl;
                float z0 = acc[mt][nt][hf * 2]     + bb0;
                float z1 = acc[mt][nt][hf * 2 + 1] + bb1;
                float r0, r1;
                if (EPI == EPI_RELU) {
                    r0 = fmaxf(z0, 0.f);
                    r1 = fmaxf(z1, 0.f);
                } else {
                    int grow = g_perm[pos];
                    __nv_bfloat162 e = *reinterpret_cast<const __nv_bfloat162*>(
                        &g_ebf[(size_t)grow * I_ + col]);
                    float w0 = 1.f / (1.f + __expf(-z0));  // sigmoid>0.5 <=> z>0
                    float w1 = 1.f / (1.f + __expf(-z1));
                    r0 = (z0 > 0.f) ? __bfloat162float(e.x) * w0 : 0.f;
                    r1 = (z1 > 0.f) ? __bfloat162float(e.y) * w1 : 0.f;
                }
                *reinterpret_cast<__nv_bfloat162*>(&C[(size_t)pos * ldc + col]) =
                    __floats2bfloat162_rn(r0, r1);
            }
        }
    }
}

// ---------------- final 128-dot + sigmoid + scatter -----------------------
__global__ void final_kernel(const float* __restrict__ w4,
                             const float* __restrict__ b4,
                             float* __restrict__ out)
{
    int row  = blockIdx.x * 8 + (threadIdx.x >> 5);
    int lane = threadIdx.x & 31;
    const __nv_bfloat16* x = g_x3 + (size_t)row * U3_ + lane * 4;
    __nv_bfloat162 x01 = *reinterpret_cast<const __nv_bfloat162*>(x);
    __nv_bfloat162 x23 = *reinterpret_cast<const __nv_bfloat162*>(x + 2);
    float4 w = *reinterpret_cast<const float4*>(w4 + lane * 4);
    float s = __bfloat162float(x01.x) * w.x + __bfloat162float(x01.y) * w.y
            + __bfloat162float(x23.x) * w.z + __bfloat162float(x23.y) * w.w;
#pragma unroll
    for (int o = 16; o; o >>= 1) s += __shfl_xor_sync(0xffffffffu, s, o);
    if (lane == 0)
        out[g_perm[row]] = 1.f / (1.f + expf(-(s + b4[0])));
}

// ---------------- launch ---------------------------------------------------
static inline int cdiv4_256(int n) { return (n / 4 + 255) / 256; }

extern "C" void kernel_launch(void* const* d_in, const int* in_sizes, int n_in,
                              void* d_out, int out_size)
{
    const float* emb  = (const float*)d_in[0];
    const int*   dom  = (const int*)  d_in[1];
    const float* p_w1 = (const float*)d_in[2];
    const float* p_b1 = (const float*)d_in[3];
    const float* p_w2 = (const float*)d_in[4];
    const float* p_b2 = (const float*)d_in[5];
    const float* d_w1 = (const float*)d_in[6];
    const float* d_b1 = (const float*)d_in[7];
    const float* d_w2 = (const float*)d_in[8];
    const float* d_b2 = (const float*)d_in[9];
    const float* d_w3 = (const float*)d_in[10];
    const float* d_b3 = (const float*)d_in[11];
    const float* d_w4 = (const float*)d_in[12];
    const float* d_b4 = (const float*)d_in[13];
    float* out = (float*)d_out;

    // 0) fp32 -> bf16 conversions
    f2bf<<<cdiv4_256(B_ * I_),      256>>>(emb,  5, B_ * I_);
    f2bf<<<cdiv4_256(D_ * I_ * H_), 256>>>(p_w1, 6, D_ * I_ * H_);
    f2bf<<<cdiv4_256(D_ * H_ * I_), 256>>>(p_w2, 7, D_ * H_ * I_);
    f2bf<<<cdiv4_256(I_ * U1_),     256>>>(d_w1, 8, I_ * U1_);
    f2bf<<<cdiv4_256(U1_ * U2_),    256>>>(d_w2, 9, U1_ * U2_);
    f2bf<<<cdiv4_256(U2_ * U3_),    256>>>(d_w3, 10, U2_ * U3_);

    // 1) bin rows by domain
    k_init   <<<1, 32>>>();
    k_count  <<<(B_ + 255) / 256, 256>>>(dom);
    k_scan   <<<1, 32>>>();
    k_scatter<<<(B_ + 255) / 256, 256>>>(dom);

    // 2) pruner layer 1: h = relu(emb[perm] @ p_w1[d] + p_b1[d])   [B,320]
    gemm_bf16<true, true, EPI_RELU>
        <<<dim3(H_ / 64, B_ / 128, D_), 256>>>(
            5, I_, 6, (long)I_ * H_, p_b1, H_, /*cid=*/0, H_, H_, I_);

    // 3) pruner layer 2 + prune: s = emb * sigmoid(z) * (z>0)       [B,1280]
    gemm_bf16<true, false, EPI_PRUNE>
        <<<dim3(I_ / 64, B_ / 128, D_), 256>>>(
            0, H_, 7, (long)H_ * I_, p_b2, I_, /*cid=*/1, I_, I_, H_);

    // 4) shared MLP
    gemm_bf16<false, false, EPI_RELU>
        <<<dim3(U1_ / 64, B_ / 128, 1), 256>>>(
            1, I_, 8, 0, d_b1, 0, /*cid=*/2, U1_, U1_, I_);
    gemm_bf16<false, false, EPI_RELU>
        <<<dim3(U2_ / 64, B_ / 128, 1), 256>>>(
            2, U1_, 9, 0, d_b2, 0, /*cid=*/3, U2_, U2_, U1_);
    gemm_bf16<false, false, EPI_RELU>
        <<<dim3(U3_ / 64, B_ / 128, 1), 256>>>(
            3, U2_, 10, 0, d_b3, 0, /*cid=*/4, U3_, U3_, U2_);

    // 5) logits + sigmoid + scatter to original rows
    final_kernel<<<B_ / 8, 256>>>(d_w4, d_b4, out);
}

// round 6
// speedup vs baseline: 3.9621x; 1.1016x over previous
#include <cuda_runtime.h>
#include <cuda_bf16.h>
#include <cstdint>
#include <math.h>

#define B_  16384
#define I_  1280
#define H_  320
#define D_  4
#define U1_ 512
#define U2_ 256
#define U3_ 128

// ---------------- scratch (device globals; no allocation allowed) ----------
__device__ int g_perm[B_];
__device__ int g_count[D_], g_base[D_];

__device__ __nv_bfloat16 g_h  [B_ * H_];
__device__ __nv_bfloat16 g_s  [B_ * I_];
__device__ __nv_bfloat16 g_x1 [B_ * U1_];
__device__ __nv_bfloat16 g_x2 [B_ * U2_];
__device__ __nv_bfloat16 g_x3 [B_ * U3_];
__device__ __nv_bfloat16 g_ebf[B_ * I_];
__device__ __nv_bfloat16 g_pw1[D_ * I_ * H_];
__device__ __nv_bfloat16 g_pw2[D_ * H_ * I_];
__device__ __nv_bfloat16 g_dw1[I_ * U1_];
__device__ __nv_bfloat16 g_dw2[U1_ * U2_];
__device__ __nv_bfloat16 g_dw3[U2_ * U3_];

__device__ __forceinline__ __nv_bfloat16* bfbuf(int id) {
    switch (id) {
        case 0: return g_h;   case 1: return g_s;   case 2: return g_x1;
        case 3: return g_x2;  case 4: return g_x3;  case 5: return g_ebf;
        case 6: return g_pw1; case 7: return g_pw2; case 8: return g_dw1;
        case 9: return g_dw2; case 10: return g_dw3;
    }
    return nullptr;
}

// ---------------- fp32 -> bf16 conversion ----------------------------------
__global__ void f2bf(const float* __restrict__ src, int dstid, int n) {
    int i = (blockIdx.x * 256 + threadIdx.x) * 4;
    if (i >= n) return;
    float4 v = *reinterpret_cast<const float4*>(src + i);
    __nv_bfloat16* d = bfbuf(dstid) + i;
    *reinterpret_cast<__nv_bfloat162*>(d)     = __floats2bfloat162_rn(v.x, v.y);
    *reinterpret_cast<__nv_bfloat162*>(d + 2) = __floats2bfloat162_rn(v.z, v.w);
}

// ---------------- fused domain binning (single block) ----------------------
// counting sort by domain; order within a domain is irrelevant (all rows of a
// domain share weights, per-row math independent) -> deterministic output.
__global__ __launch_bounds__(1024) void k_bin(const int* __restrict__ dom) {
    __shared__ int cnt[D_], base[D_];
    const int t = threadIdx.x;
    if (t < D_) cnt[t] = 0;
    __syncthreads();
    for (int i = t; i < B_; i += 1024) {
        int d = dom[i]; d = d < 0 ? 0 : (d > D_ - 1 ? D_ - 1 : d);
        atomicAdd(&cnt[d], 1);
    }
    __syncthreads();
    if (t == 0) {
        int s = 0;
        for (int d = 0; d < D_; d++) {
            base[d] = s; g_base[d] = s; g_count[d] = cnt[d]; s += cnt[d];
        }
    }
    __syncthreads();
    if (t < D_) cnt[t] = 0;      // reuse as cursors
    __syncthreads();
    for (int i = t; i < B_; i += 1024) {
        int d = dom[i]; d = d < 0 ? 0 : (d > D_ - 1 ? D_ - 1 : d);
        int p = base[d] + atomicAdd(&cnt[d], 1);
        g_perm[p] = i;
    }
}

// ---------------- tensor-core / async-copy primitives ----------------------
__device__ __forceinline__ void ldsm4(uint32_t& r0, uint32_t& r1,
                                      uint32_t& r2, uint32_t& r3, uint32_t a) {
    asm volatile("ldmatrix.sync.aligned.m8n8.x4.shared.b16 {%0,%1,%2,%3}, [%4];"
                 : "=r"(r0), "=r"(r1), "=r"(r2), "=r"(r3) : "r"(a));
}
__device__ __forceinline__ void ldsm4t(uint32_t& r0, uint32_t& r1,
                                       uint32_t& r2, uint32_t& r3, uint32_t a) {
    asm volatile("ldmatrix.sync.aligned.m8n8.x4.trans.shared.b16 {%0,%1,%2,%3}, [%4];"
                 : "=r"(r0), "=r"(r1), "=r"(r2), "=r"(r3) : "r"(a));
}
__device__ __forceinline__ void mma_bf16(float* c,
                                         uint32_t a0, uint32_t a1, uint32_t a2, uint32_t a3,
                                         uint32_t b0, uint32_t b1) {
    asm volatile("mma.sync.aligned.m16n8k16.row.col.f32.bf16.bf16.f32 "
                 "{%0,%1,%2,%3}, {%4,%5,%6,%7}, {%8,%9}, {%0,%1,%2,%3};"
                 : "+f"(c[0]), "+f"(c[1]), "+f"(c[2]), "+f"(c[3])
                 : "r"(a0), "r"(a1), "r"(a2), "r"(a3), "r"(b0), "r"(b1));
}
// 16B async copy; pred=false -> zero-fill (ignore-src), no gmem read.
__device__ __forceinline__ void cp16(uint32_t dst, const void* src, bool pred) {
    int sz = pred ? 16 : 0;
    asm volatile("cp.async.cg.shared.global [%0], [%1], 16, %2;"
                 :: "r"(dst), "l"(src), "r"(sz));
}
__device__ __forceinline__ void cp_commit() {
    asm volatile("cp.async.commit_group;");
}
template<int N>
__device__ __forceinline__ void cp_wait() {
    asm volatile("cp.async.wait_group %0;" :: "n"(N));
}

// ---------------- bf16 tensor-core GEMM (cp.async 3-stage) ------------------
// C[M,N](bf16) = epilogue(A[M,K](bf16) @ W[K,N](bf16) + bias(fp32))
// Block tile 128x64x32, 256 threads = 8 warps (4x2), warp tile 32x32,
// mma m16n8k16, fp32 accum. 3-stage cp.async pipeline, 2 tiles in flight.
// A smem rows padded to 40 elems (80B), B rows to 72 elems (144B):
// conflict-free ldmatrix, cp.async-16B-aligned.
#define EPI_RELU  0
#define EPI_PRUNE 1
#define LDA_PAD 40
#define LDB_PAD 72
#define STG 3

template<bool SEG, bool GATHER, int EPI>
__global__ __launch_bounds__(256)
void gemm_bf16(int aid, int lda, int wid, long wstride,
               const float* __restrict__ bias, int bstride,
               int cid, int ldc, int N, int K)
{
    __shared__ __nv_bfloat16 As[STG][128 * LDA_PAD];
    __shared__ __nv_bfloat16 Bs[STG][32 * LDB_PAD];

    const int t = threadIdx.x;
    int bz = SEG ? blockIdx.z : 0;
    int segBase = 0, segCnt = B_;
    if (SEG) { segCnt = g_count[bz]; segBase = g_base[bz]; }

    const int m0 = blockIdx.y * 128;
    if (m0 >= segCnt) return;                 // uniform per block
    const int n0 = blockIdx.x * 64;

    const __nv_bfloat16* A  = bfbuf(aid);
    const __nv_bfloat16* Wp = bfbuf(wid) + (long)bz * wstride;
    const float*         bp = bias + bz * bstride;

    // ---- staging roles ----
    // A: 512 16B-chunks (128 rows x 4); thread t handles chunks t and t+256.
    const int  ar0 = t >> 2, ar1 = 64 + (t >> 2);
    const int  ac8 = (t & 3) * 8;
    const bool v0 = (m0 + ar0) < segCnt, v1 = (m0 + ar1) < segCnt;
    const __nv_bfloat16 *Ap0 = A, *Ap1 = A;  // valid-base fallback (no read when !v)
    if (v0) {
        int p = segBase + m0 + ar0;
        int gr = GATHER ? g_perm[p] : p;
        Ap0 = A + (size_t)gr * lda;
    }
    if (v1) {
        int p = segBase + m0 + ar1;
        int gr = GATHER ? g_perm[p] : p;
        Ap1 = A + (size_t)gr * lda;
    }
    // B: 256 16B-chunks (32 rows x 8); thread t handles chunk t.
    const int br = t >> 3, bc8 = (t & 7) * 8;
    const __nv_bfloat16* Bg = Wp + (size_t)br * N + n0 + bc8;

    // per-stage smem byte addresses
    uint32_t aDst[STG], bDst[STG], aBase[STG], bBase[STG];
#pragma unroll
    for (int s = 0; s < STG; s++) {
        aBase[s] = (uint32_t)__cvta_generic_to_shared(&As[s][0]);
        bBase[s] = (uint32_t)__cvta_generic_to_shared(&Bs[s][0]);
        aDst[s]  = aBase[s] + ((ar0 * LDA_PAD + ac8) << 1);
        bDst[s]  = bBase[s] + ((br  * LDB_PAD + bc8) << 1);
    }
    const uint32_t aDstOff = (uint32_t)((ar1 - ar0) * LDA_PAD) << 1;

    const int kIters = K / 32;

    // ---- issue helper (stage = i % STG) ----
    auto issue = [&](int i) {
        int s = i % STG;
        const __nv_bfloat16* a0 = Ap0 + i * 32 + ac8;
        const __nv_bfloat16* a1 = Ap1 + i * 32 + ac8;
        cp16(aDst[s],           a0, v0);
        cp16(aDst[s] + aDstOff, a1, v1);
        cp16(bDst[s], Bg + (size_t)i * 32 * N, true);
        cp_commit();
    };

    issue(0);
    if (kIters > 1) issue(1);

    const int lane = t & 31, warp = t >> 5;
    const int wm = warp >> 1, wn = warp & 1;        // 4x2 warp grid
    const int aRowOff = lane & 15;                  // + wm*32 + mt*16
    const int aColOff = (lane >> 4) * 8;            // + ks*16
    const int bRowOff = (lane & 7) + ((lane >> 3) & 1) * 8;  // + ks*16
    const int bColOff = wn * 32 + (lane >> 4) * 8;  // + np*16

    float acc[2][4][4];
#pragma unroll
    for (int i = 0; i < 2; i++)
#pragma unroll
        for (int j = 0; j < 4; j++)
#pragma unroll
            for (int k = 0; k < 4; k++) acc[i][j][k] = 0.f;

    for (int i = 0; i < kIters; i++) {
        if (i + 1 < kIters) cp_wait<1>(); else cp_wait<0>();
        __syncthreads();

        if (i + STG - 1 < kIters) issue(i + STG - 1);

        const int s = i % STG;
        const uint32_t bA = aBase[s], bB = bBase[s];
#pragma unroll
        for (int ks = 0; ks < 2; ks++) {
            uint32_t a[2][4], b[2][4];
#pragma unroll
            for (int mt = 0; mt < 2; mt++) {
                uint32_t addr = bA +
                    (((wm * 32 + mt * 16 + aRowOff) * LDA_PAD + ks * 16 + aColOff) << 1);
                ldsm4(a[mt][0], a[mt][1], a[mt][2], a[mt][3], addr);
            }
#pragma unroll
            for (int np = 0; np < 2; np++) {
                uint32_t addr = bB +
                    (((ks * 16 + bRowOff) * LDB_PAD + bColOff + np * 16) << 1);
                ldsm4t(b[np][0], b[np][1], b[np][2], b[np][3], addr);
            }
#pragma unroll
            for (int mt = 0; mt < 2; mt++)
#pragma unroll
                for (int np = 0; np < 2; np++) {
                    mma_bf16(acc[mt][np * 2],
                             a[mt][0], a[mt][1], a[mt][2], a[mt][3],
                             b[np][0], b[np][1]);
                    mma_bf16(acc[mt][np * 2 + 1],
                             a[mt][0], a[mt][1], a[mt][2], a[mt][3],
                             b[np][2], b[np][3]);
                }
        }
        // next iteration's wait+sync protects stage reuse; no extra barrier here
        __syncthreads();
    }

    // ---- epilogue ----
    __nv_bfloat16* C = bfbuf(cid);
    const int g = lane >> 2, tig = lane & 3;
#pragma unroll
    for (int mt = 0; mt < 2; mt++) {
#pragma unroll
        for (int nt = 0; nt < 4; nt++) {
            const int col = n0 + wn * 32 + nt * 8 + tig * 2;
            const float bb0 = bp[col], bb1 = bp[col + 1];
#pragma unroll
            for (int hf = 0; hf < 2; hf++) {
                const int rl = wm * 32 + mt * 16 + g + hf * 8;
                if (m0 + rl >= segCnt) continue;
                const int pos = segBase + m0 + rl;
                float z0 = acc[mt][nt][hf * 2]     + bb0;
                float z1 = acc[mt][nt][hf * 2 + 1] + bb1;
                float r0, r1;
                if (EPI == EPI_RELU) {
                    r0 = fmaxf(z0, 0.f);
                    r1 = fmaxf(z1, 0.f);
                } else {
                    int grow = g_perm[pos];
                    __nv_bfloat162 e = *reinterpret_cast<const __nv_bfloat162*>(
                        &g_ebf[(size_t)grow * I_ + col]);
                    float w0 = 1.f / (1.f + __expf(-z0));  // sigmoid>0.5 <=> z>0
                    float w1 = 1.f / (1.f + __expf(-z1));
                    r0 = (z0 > 0.f) ? __bfloat162float(e.x) * w0 : 0.f;
                    r1 = (z1 > 0.f) ? __bfloat162float(e.y) * w1 : 0.f;
                }
                *reinterpret_cast<__nv_bfloat162*>(&C[(size_t)pos * ldc + col]) =
                    __floats2bfloat162_rn(r0, r1);
            }
        }
    }
}

// ---------------- final 128-dot + sigmoid + scatter -----------------------
__global__ void final_kernel(const float* __restrict__ w4,
                             const float* __restrict__ b4,
                             float* __restrict__ out)
{
    int row  = blockIdx.x * 8 + (threadIdx.x >> 5);
    int lane = threadIdx.x & 31;
    const __nv_bfloat16* x = g_x3 + (size_t)row * U3_ + lane * 4;
    __nv_bfloat162 x01 = *reinterpret_cast<const __nv_bfloat162*>(x);
    __nv_bfloat162 x23 = *reinterpret_cast<const __nv_bfloat162*>(x + 2);
    float4 w = *reinterpret_cast<const float4*>(w4 + lane * 4);
    float s = __bfloat162float(x01.x) * w.x + __bfloat162float(x01.y) * w.y
            + __bfloat162float(x23.x) * w.z + __bfloat162float(x23.y) * w.w;
#pragma unroll
    for (int o = 16; o; o >>= 1) s += __shfl_xor_sync(0xffffffffu, s, o);
    if (lane == 0)
        out[g_perm[row]] = 1.f / (1.f + expf(-(s + b4[0])));
}

// ---------------- launch ---------------------------------------------------
static inline int cdiv4_256(int n) { return (n / 4 + 255) / 256; }

extern "C" void kernel_launch(void* const* d_in, const int* in_sizes, int n_in,
                              void* d_out, int out_size)
{
    const float* emb  = (const float*)d_in[0];
    const int*   dom  = (const int*)  d_in[1];
    const float* p_w1 = (const float*)d_in[2];
    const float* p_b1 = (const float*)d_in[3];
    const float* p_w2 = (const float*)d_in[4];
    const float* p_b2 = (const float*)d_in[5];
    const float* d_w1 = (const float*)d_in[6];
    const float* d_b1 = (const float*)d_in[7];
    const float* d_w2 = (const float*)d_in[8];
    const float* d_b2 = (const float*)d_in[9];
    const float* d_w3 = (const float*)d_in[10];
    const float* d_b3 = (const float*)d_in[11];
    const float* d_w4 = (const float*)d_in[12];
    const float* d_b4 = (const float*)d_in[13];
    float* out = (float*)d_out;

    // launches ordered so ncu (-s 5 -c 1) profiles gemm1 (launch #6)
    k_bin<<<1, 1024>>>(dom);                                     // 1
    f2bf<<<cdiv4_256(B_ * I_),      256>>>(emb,  5, B_ * I_);    // 2
    f2bf<<<cdiv4_256(D_ * I_ * H_), 256>>>(p_w1, 6, D_ * I_ * H_); // 3
    f2bf<<<cdiv4_256(D_ * H_ * I_), 256>>>(p_w2, 7, D_ * H_ * I_); // 4
    f2bf<<<cdiv4_256(I_ * U1_),     256>>>(d_w1, 8, I_ * U1_);   // 5

    // 6: pruner layer 1: h = relu(emb[perm] @ p_w1[d] + p_b1[d])  [B,320]
    gemm_bf16<true, true, EPI_RELU>
        <<<dim3(H_ / 64, B_ / 128, D_), 256>>>(
            5, I_, 6, (long)I_ * H_, p_b1, H_, /*cid=*/0, H_, H_, I_);

    f2bf<<<cdiv4_256(U1_ * U2_), 256>>>(d_w2, 9, U1_ * U2_);     // 7
    f2bf<<<cdiv4_256(U2_ * U3_), 256>>>(d_w3, 10, U2_ * U3_);    // 8

    // pruner layer 2 + prune: s = emb * sigmoid(z) * (z>0)        [B,1280]
    gemm_bf16<true, false, EPI_PRUNE>
        <<<dim3(I_ / 64, B_ / 128, D_), 256>>>(
            0, H_, 7, (long)H_ * I_, p_b2, I_, /*cid=*/1, I_, I_, H_);

    // shared MLP
    gemm_bf16<false, false, EPI_RELU>
        <<<dim3(U1_ / 64, B_ / 128, 1), 256>>>(
            1, I_, 8, 0, d_b1, 0, /*cid=*/2, U1_, U1_, I_);
    gemm_bf16<false, false, EPI_RELU>
        <<<dim3(U2_ / 64, B_ / 128, 1), 256>>>(
            2, U1_, 9, 0, d_b2, 0, /*cid=*/3, U2_, U2_, U1_);
    gemm_bf16<false, false, EPI_RELU>
        <<<dim3(U3_ / 64, B_ / 128, 1), 256>>>(
            3, U2_, 10, 0, d_b3, 0, /*cid=*/4, U3_, U3_, U2_);

    // logits + sigmoid + scatter to original rows
    final_kernel<<<B_ / 8, 256>>>(d_w4, d_b4, out);
}

// round 8
// speedup vs baseline: 4.0882x; 1.0318x over previous
#include <cuda_runtime.h>
#include <cuda_bf16.h>
#include <cstdint>
#include <math.h>

#define B_  16384
#define I_  1280
#define H_  320
#define D_  4
#define U1_ 512
#define U2_ 256
#define U3_ 128

// ---------------- scratch (device globals; no allocation allowed) ----------
__device__ int g_perm[B_];
__device__ int g_count[D_], g_base[D_];

__device__ __nv_bfloat16 g_h  [B_ * H_];
__device__ __nv_bfloat16 g_s  [B_ * I_];
__device__ __nv_bfloat16 g_x1 [B_ * U1_];
__device__ __nv_bfloat16 g_x2 [B_ * U2_];
__device__ __nv_bfloat16 g_x3 [B_ * U3_];
__device__ __nv_bfloat16 g_ebf[B_ * I_];
__device__ __nv_bfloat16 g_pw1[D_ * I_ * H_];
__device__ __nv_bfloat16 g_pw2[D_ * H_ * I_];
__device__ __nv_bfloat16 g_dw1[I_ * U1_];
__device__ __nv_bfloat16 g_dw2[U1_ * U2_];
__device__ __nv_bfloat16 g_dw3[U2_ * U3_];

__device__ __forceinline__ __nv_bfloat16* bfbuf(int id) {
    switch (id) {
        case 0: return g_h;   case 1: return g_s;   case 2: return g_x1;
        case 3: return g_x2;  case 4: return g_x3;  case 5: return g_ebf;
        case 6: return g_pw1; case 7: return g_pw2; case 8: return g_dw1;
        case 9: return g_dw2; case 10: return g_dw3;
    }
    return nullptr;
}

// ---------------- fp32 -> bf16 conversion ----------------------------------
__device__ __forceinline__ void cvt4(const float* __restrict__ s,
                                     __nv_bfloat16* __restrict__ d, int i) {
    float4 v = *reinterpret_cast<const float4*>(s + i);
    *reinterpret_cast<__nv_bfloat162*>(d + i)     = __floats2bfloat162_rn(v.x, v.y);
    *reinterpret_cast<__nv_bfloat162*>(d + i + 2) = __floats2bfloat162_rn(v.z, v.w);
}

__global__ void f2bf(const float* __restrict__ src, int dstid, int n) {
    int i = (blockIdx.x * 256 + threadIdx.x) * 4;
    if (i >= n) return;
    cvt4(src, bfbuf(dstid), i);
}

// all 5 weight tensors in one launch (4,096,000 elems total, all 4-divisible)
// NOTE: cvt4 indexes src AND dst by the same i -> pass segment-LOCAL index.
#define NW1 (D_ * I_ * H_)            // 1,638,400 -> g_pw1
#define NW2 (NW1 + D_ * H_ * I_)      // 3,276,800 -> g_pw2
#define NW3 (NW2 + I_ * U1_)          // 3,932,160 -> g_dw1
#define NW4 (NW3 + U1_ * U2_)         // 4,063,232 -> g_dw2
#define NW5 (NW4 + U2_ * U3_)         // 4,096,000 -> g_dw3
__global__ void f2bf_all(const float* __restrict__ s0, const float* __restrict__ s1,
                         const float* __restrict__ s2, const float* __restrict__ s3,
                         const float* __restrict__ s4) {
    int i = (blockIdx.x * 256 + threadIdx.x) * 4;
    if (i < NW1)      cvt4(s0, g_pw1, i);
    else if (i < NW2) cvt4(s1, g_pw2, i - NW1);
    else if (i < NW3) cvt4(s2, g_dw1, i - NW2);
    else if (i < NW4) cvt4(s3, g_dw2, i - NW3);
    else if (i < NW5) cvt4(s4, g_dw3, i - NW4);
}

// ---------------- fused domain binning (single block) ----------------------
__global__ __launch_bounds__(1024) void k_bin(const int* __restrict__ dom) {
    __shared__ int cnt[D_], base[D_];
    const int t = threadIdx.x;
    if (t < D_) cnt[t] = 0;
    __syncthreads();
    for (int i = t; i < B_; i += 1024) {
        int d = dom[i]; d = d < 0 ? 0 : (d > D_ - 1 ? D_ - 1 : d);
        atomicAdd(&cnt[d], 1);
    }
    __syncthreads();
    if (t == 0) {
        int s = 0;
        for (int d = 0; d < D_; d++) {
            base[d] = s; g_base[d] = s; g_count[d] = cnt[d]; s += cnt[d];
        }
    }
    __syncthreads();
    if (t < D_) cnt[t] = 0;      // reuse as cursors
    __syncthreads();
    for (int i = t; i < B_; i += 1024) {
        int d = dom[i]; d = d < 0 ? 0 : (d > D_ - 1 ? D_ - 1 : d);
        int p = base[d] + atomicAdd(&cnt[d], 1);
        g_perm[p] = i;
    }
}

// ---------------- tensor-core / async-copy primitives ----------------------
__device__ __forceinline__ void ldsm4(uint32_t& r0, uint32_t& r1,
                                      uint32_t& r2, uint32_t& r3, uint32_t a) {
    asm volatile("ldmatrix.sync.aligned.m8n8.x4.shared.b16 {%0,%1,%2,%3}, [%4];"
                 : "=r"(r0), "=r"(r1), "=r"(r2), "=r"(r3) : "r"(a));
}
__device__ __forceinline__ void ldsm4t(uint32_t& r0, uint32_t& r1,
                                       uint32_t& r2, uint32_t& r3, uint32_t a) {
    asm volatile("ldmatrix.sync.aligned.m8n8.x4.trans.shared.b16 {%0,%1,%2,%3}, [%4];"
                 : "=r"(r0), "=r"(r1), "=r"(r2), "=r"(r3) : "r"(a));
}
__device__ __forceinline__ void mma_bf16(float* c,
                                         uint32_t a0, uint32_t a1, uint32_t a2, uint32_t a3,
                                         uint32_t b0, uint32_t b1) {
    asm volatile("mma.sync.aligned.m16n8k16.row.col.f32.bf16.bf16.f32 "
                 "{%0,%1,%2,%3}, {%4,%5,%6,%7}, {%8,%9}, {%0,%1,%2,%3};"
                 : "+f"(c[0]), "+f"(c[1]), "+f"(c[2]), "+f"(c[3])
                 : "r"(a0), "r"(a1), "r"(a2), "r"(a3), "r"(b0), "r"(b1));
}
__device__ __forceinline__ void cp16(uint32_t dst, const void* src, bool pred) {
    int sz = pred ? 16 : 0;
    asm volatile("cp.async.cg.shared.global [%0], [%1], 16, %2;"
                 :: "r"(dst), "l"(src), "r"(sz));
}
__device__ __forceinline__ void cp_commit() {
    asm volatile("cp.async.commit_group;");
}
template<int N>
__device__ __forceinline__ void cp_wait() {
    asm volatile("cp.async.wait_group %0;" :: "n"(N));
}

// ---------------- bf16 tensor-core GEMM (cp.async 3-stage) ------------------
// Block tile 128 x TN x 32, 256 threads = 8 warps; warp tile 32 x (TN/2).
// 3-stage cp.async pipeline, ONE __syncthreads per k-iter.
// A smem rows padded to 40 elems (80B), B rows to TN+8 elems: conflict-free.
#define EPI_RELU  0
#define EPI_PRUNE 1
#define LDA_PAD 40
#define STG 3

template<int TN, bool SEG, bool GATHER, int EPI>
__global__ __launch_bounds__(256, 2)
void gemm_bf16(int aid, int lda, int wid, long wstride,
               const float* __restrict__ bias, int bstride,
               int cid, int ldc, int N, int K)
{
    constexpr int LDBP = TN + 8;       // B smem row pitch (elems)
    constexpr int WN   = TN / 2;       // warp n extent
    constexpr int NP   = WN / 16;      // ldsm4t per ks
    constexpr int NACC = WN / 8;       // 8-col acc groups per warp
    constexpr int TNC  = TN / 8;       // 16B chunks per B row
    constexpr int NB   = (4 * TN) / 256;  // B chunks per thread

    extern __shared__ char smem_raw[];
    __nv_bfloat16* Asm = reinterpret_cast<__nv_bfloat16*>(smem_raw);
    __nv_bfloat16* Bsm = reinterpret_cast<__nv_bfloat16*>(
        smem_raw + (size_t)STG * 128 * LDA_PAD * 2);

    const int t = threadIdx.x;
    int bz = SEG ? blockIdx.z : 0;
    int segBase = 0, segCnt = B_;
    if (SEG) { segCnt = g_count[bz]; segBase = g_base[bz]; }

    const int m0 = blockIdx.y * 128;
    if (m0 >= segCnt) return;                 // uniform per block
    const int n0 = blockIdx.x * TN;

    const __nv_bfloat16* A  = bfbuf(aid);
    const __nv_bfloat16* Wp = bfbuf(wid) + (long)bz * wstride;
    const float*         bp = bias + bz * bstride;

    // ---- A staging roles: 512 chunks (128 rows x 4); thread t: t, t+256 ----
    const int  ar0 = t >> 2, ar1 = 64 + (t >> 2);
    const int  ac8 = (t & 3) * 8;
    const bool v0 = (m0 + ar0) < segCnt, v1 = (m0 + ar1) < segCnt;
    const __nv_bfloat16 *Ap0 = A, *Ap1 = A;   // fallback base (no read if !v)
    if (v0) {
        int p = segBase + m0 + ar0;
        int gr = GATHER ? g_perm[p] : p;
        Ap0 = A + (size_t)gr * lda;
    }
    if (v1) {
        int p = segBase + m0 + ar1;
        int gr = GATHER ? g_perm[p] : p;
        Ap1 = A + (size_t)gr * lda;
    }
    // ---- B staging roles: 4*TN chunks; thread t handles NB of them ----
    int brow[NB], bcol[NB];
    const __nv_bfloat16* BgJ[NB];
#pragma unroll
    for (int j = 0; j < NB; j++) {
        int c = t + j * 256;
        brow[j] = c / TNC;
        bcol[j] = (c % TNC) * 8;
        BgJ[j]  = Wp + (size_t)brow[j] * N + n0 + bcol[j];
    }

    // per-stage smem byte addresses
    uint32_t aDst[STG], aBase[STG], bBase[STG];
#pragma unroll
    for (int s = 0; s < STG; s++) {
        aBase[s] = (uint32_t)__cvta_generic_to_shared(Asm + (size_t)s * 128 * LDA_PAD);
        bBase[s] = (uint32_t)__cvta_generic_to_shared(Bsm + (size_t)s * 32 * LDBP);
        aDst[s]  = aBase[s] + ((ar0 * LDA_PAD + ac8) << 1);
    }
    const uint32_t aDstOff = (uint32_t)((ar1 - ar0) * LDA_PAD) << 1;

    const int kIters = K / 32;

    auto issue = [&](int i) {
        int s = i % STG;
        cp16(aDst[s],           Ap0 + i * 32 + ac8, v0);
        cp16(aDst[s] + aDstOff, Ap1 + i * 32 + ac8, v1);
#pragma unroll
        for (int j = 0; j < NB; j++)
            cp16(bBase[s] + ((brow[j] * LDBP + bcol[j]) << 1),
                 BgJ[j] + (size_t)i * 32 * N, true);
        cp_commit();
    };

    issue(0);
    if (kIters > 1) issue(1);

    const int lane = t & 31, warp = t >> 5;
    const int wm = warp >> 1, wn = warp & 1;        // 4x2 warp grid
    const int aRowOff = lane & 15;
    const int aColOff = (lane >> 4) * 8;
    const int bRowOff = (lane & 7) + ((lane >> 3) & 1) * 8;
    const int bColOff = wn * WN + (lane >> 4) * 8;

    float acc[2][NACC][4];
#pragma unroll
    for (int i = 0; i < 2; i++)
#pragma unroll
        for (int j = 0; j < NACC; j++)
#pragma unroll
            for (int k = 0; k < 4; k++) acc[i][j][k] = 0.f;

    for (int i = 0; i < kIters; i++) {
        if (i + 1 < kIters) cp_wait<1>(); else cp_wait<0>();
        __syncthreads();   // single barrier per iter: orders reads of stage
                           // (i-1)%3 (done last iter) before issue overwrites it

        if (i + STG - 1 < kIters) issue(i + STG - 1);

        const int s = i % STG;
        const uint32_t bA = aBase[s], bB = bBase[s];
#pragma unroll
        for (int ks = 0; ks < 2; ks++) {
            uint32_t a[2][4], b[NP][4];
#pragma unroll
            for (int mt = 0; mt < 2; mt++) {
                uint32_t addr = bA +
                    (((wm * 32 + mt * 16 + aRowOff) * LDA_PAD + ks * 16 + aColOff) << 1);
                ldsm4(a[mt][0], a[mt][1], a[mt][2], a[mt][3], addr);
            }
#pragma unroll
            for (int np = 0; np < NP; np++) {
                uint32_t addr = bB +
                    (((ks * 16 + bRowOff) * LDBP + bColOff + np * 16) << 1);
                ldsm4t(b[np][0], b[np][1], b[np][2], b[np][3], addr);
            }
#pragma unroll
            for (int mt = 0; mt < 2; mt++)
#pragma unroll
                for (int np = 0; np < NP; np++) {
                    mma_bf16(acc[mt][np * 2],
                             a[mt][0], a[mt][1], a[mt][2], a[mt][3],
                             b[np][0], b[np][1]);
                    mma_bf16(acc[mt][np * 2 + 1],
                             a[mt][0], a[mt][1], a[mt][2], a[mt][3],
                             b[np][2], b[np][3]);
                }
        }
    }

    // ---- epilogue ----
    __nv_bfloat16* C = bfbuf(cid);
    const int g = lane >> 2, tig = lane & 3;
#pragma unroll
    for (int mt = 0; mt < 2; mt++) {
#pragma unroll
        for (int nt = 0; nt < NACC; nt++) {
            const int col = n0 + wn * WN + nt * 8 + tig * 2;
            const float bb0 = bp[col], bb1 = bp[col + 1];
#pragma unroll
            for (int hf = 0; hf < 2; hf++) {
                const int rl = wm * 32 + mt * 16 + g + hf * 8;
                if (m0 + rl >= segCnt) continue;
                const int pos = segBase + m0 + rl;
                float z0 = acc[mt][nt][hf * 2]     + bb0;
                float z1 = acc[mt][nt][hf * 2 + 1] + bb1;
                float r0, r1;
                if (EPI == EPI_RELU) {
                    r0 = fmaxf(z0, 0.f);
                    r1 = fmaxf(z1, 0.f);
                } else {
                    int grow = g_perm[pos];
                    __nv_bfloat162 e = *reinterpret_cast<const __nv_bfloat162*>(
                        &g_ebf[(size_t)grow * I_ + col]);
                    float w0 = 1.f / (1.f + __expf(-z0));  // sigmoid>0.5 <=> z>0
                    float w1 = 1.f / (1.f + __expf(-z1));
                    r0 = (z0 > 0.f) ? __bfloat162float(e.x) * w0 : 0.f;
                    r1 = (z1 > 0.f) ? __bfloat162float(e.y) * w1 : 0.f;
                }
                *reinterpret_cast<__nv_bfloat162*>(&C[(size_t)pos * ldc + col]) =
                    __floats2bfloat162_rn(r0, r1);
            }
        }
    }
}

// ---------------- final 128-dot + sigmoid + scatter -----------------------
__global__ void final_kernel(const float* __restrict__ w4,
                             const float* __restrict__ b4,
                             float* __restrict__ out)
{
    int row  = blockIdx.x * 8 + (threadIdx.x >> 5);
    int lane = threadIdx.x & 31;
    const __nv_bfloat16* x = g_x3 + (size_t)row * U3_ + lane * 4;
    __nv_bfloat162 x01 = *reinterpret_cast<const __nv_bfloat162*>(x);
    __nv_bfloat162 x23 = *reinterpret_cast<const __nv_bfloat162*>(x + 2);
    float4 w = *reinterpret_cast<const float4*>(w4 + lane * 4);
    float s = __bfloat162float(x01.x) * w.x + __bfloat162float(x01.y) * w.y
            + __bfloat162float(x23.x) * w.z + __bfloat162float(x23.y) * w.w;
#pragma unroll
    for (int o = 16; o; o >>= 1) s += __shfl_xor_sync(0xffffffffu, s, o);
    if (lane == 0)
        out[g_perm[row]] = 1.f / (1.f + expf(-(s + b4[0])));
}

// ---------------- launch ---------------------------------------------------
static inline int cdiv4_256(int n) { return (n / 4 + 255) / 256; }

#define SMEM64  (STG * (128 * LDA_PAD + 32 * 72)  * 2)   // 44544 B
#define SMEM128 (STG * (128 * LDA_PAD + 32 * 136) * 2)   // 56832 B

extern "C" void kernel_launch(void* const* d_in, const int* in_sizes, int n_in,
                              void* d_out, int out_size)
{
    const float* emb  = (const float*)d_in[0];
    const int*   dom  = (const int*)  d_in[1];
    const float* p_w1 = (const float*)d_in[2];
    const float* p_b1 = (const float*)d_in[3];
    const float* p_w2 = (const float*)d_in[4];
    const float* p_b2 = (const float*)d_in[5];
    const float* d_w1 = (const float*)d_in[6];
    const float* d_b1 = (const float*)d_in[7];
    const float* d_w2 = (const float*)d_in[8];
    const float* d_b2 = (const float*)d_in[9];
    const float* d_w3 = (const float*)d_in[10];
    const float* d_b3 = (const float*)d_in[11];
    const float* d_w4 = (const float*)d_in[12];
    const float* d_b4 = (const float*)d_in[13];
    float* out = (float*)d_out;

    // allow >48KB dynamic smem for TN=128 instantiations (idempotent)
    cudaFuncSetAttribute(gemm_bf16<128, true,  false, EPI_PRUNE>,
                         cudaFuncAttributeMaxDynamicSharedMemorySize, SMEM128);
    cudaFuncSetAttribute(gemm_bf16<128, false, false, EPI_RELU>,
                         cudaFuncAttributeMaxDynamicSharedMemorySize, SMEM128);

    // 1-3: binning + conversions
    k_bin<<<1, 1024>>>(dom);
    f2bf<<<cdiv4_256(B_ * I_), 256>>>(emb, 5, B_ * I_);
    f2bf_all<<<NW5 / 4 / 256, 256>>>(p_w1, p_w2, d_w1, d_w2, d_w3);

    // 4: pruner layer 1: h = relu(emb[perm] @ p_w1[d] + p_b1[d])   [B,320]
    gemm_bf16<64, true, true, EPI_RELU>
        <<<dim3(H_ / 64, B_ / 128, D_), 256, SMEM64>>>(
            5, I_, 6, (long)I_ * H_, p_b1, H_, /*cid=*/0, H_, H_, I_);

    // 5: pruner layer 2 + prune: s = emb * sigmoid(z) * (z>0)       [B,1280]
    gemm_bf16<128, true, false, EPI_PRUNE>
        <<<dim3(I_ / 128, B_ / 128, D_), 256, SMEM128>>>(
            0, H_, 7, (long)H_ * I_, p_b2, I_, /*cid=*/1, I_, I_, H_);

    // 6-8: shared MLP
    gemm_bf16<128, false, false, EPI_RELU>
        <<<dim3(U1_ / 128, B_ / 128, 1), 256, SMEM128>>>(
            1, I_, 8, 0, d_b1, 0, /*cid=*/2, U1_, U1_, I_);
    gemm_bf16<128, false, false, EPI_RELU>
        <<<dim3(U2_ / 128, B_ / 128, 1), 256, SMEM128>>>(
            2, U1_, 9, 0, d_b2, 0, /*cid=*/3, U2_, U2_, U1_);
    gemm_bf16<128, false, false, EPI_RELU>
        <<<dim3(U3_ / 128, B_ / 128, 1), 256, SMEM128>>>(
            3, U2_, 10, 0, d_b3, 0, /*cid=*/4, U3_, U3_, U2_);

    // 9: logits + sigmoid + scatter to original rows
    final_kernel<<<B_ / 8, 256>>>(d_w4, d_b4, out);
}